// round 2
// baseline (speedup 1.0000x reference)
#include <cuda_runtime.h>
#include <cuda_bf16.h>

constexpr int B = 65536;
constexpr int C = 1000;
constexpr float INV_NEG_T = -1.0f / 0.3f;   // -1/TEMPERATURE

constexpr int MAIN_THREADS = 256;
constexpr int WARPS_PER_BLOCK = MAIN_THREADS / 32;
constexpr int MAIN_BLOCKS = B / WARPS_PER_BLOCK;   // 8192, one row per warp

// Scratch (device globals: no allocation allowed in kernel_launch)
__device__ float g_S[C * C];            // soft target matrix, 4 MB
__device__ float g_partials[MAIN_BLOCKS];

// ---------------------------------------------------------------------------
// Kernel 1: S[t,c] = softmax_c(-sim[t,c]/T). One block per class row t.
// ---------------------------------------------------------------------------
__global__ void soft_targets_kernel(const float* __restrict__ sim) {
    const int t = blockIdx.x;
    const float* row = sim + (size_t)t * C;
    __shared__ float red[256];

    float lsum = 0.0f;
    for (int c = threadIdx.x; c < C; c += 256)
        lsum += __expf(row[c] * INV_NEG_T);

    red[threadIdx.x] = lsum;
    __syncthreads();
    for (int s = 128; s > 0; s >>= 1) {
        if (threadIdx.x < s) red[threadIdx.x] += red[threadIdx.x + s];
        __syncthreads();
    }
    const float inv = 1.0f / red[0];

    for (int c = threadIdx.x; c < C; c += 256)
        g_S[(size_t)t * C + c] = __expf(row[c] * INV_NEG_T) * inv;
}

// ---------------------------------------------------------------------------
// Kernel 2: per-row loss_b = log(sum exp(x)) - dot(S[t_b], x).
// One warp per row; float4 loads (row stride 4000 B is 16B aligned).
// Block writes one partial sum (avoids same-address atomic serialization).
// Targets are int32 (JAX downcasts int64 without x64 enabled).
// ---------------------------------------------------------------------------
__global__ __launch_bounds__(MAIN_THREADS)
void soft_ce_main_kernel(const float* __restrict__ logits,
                         const int* __restrict__ targets) {
    const int warp_in_blk = threadIdx.x >> 5;
    const int lane = threadIdx.x & 31;
    const int row = blockIdx.x * WARPS_PER_BLOCK + warp_in_blk;

    const float4* lp = (const float4*)(logits + (size_t)row * C);
    int t = targets[row];
    t = (t < 0) ? 0 : ((t >= C) ? C - 1 : t);   // safety clamp (no-op if data valid)
    const float4* sp = (const float4*)(g_S + (size_t)t * C);

    float sum = 0.0f, dot = 0.0f;
    #pragma unroll
    for (int k = 0; k < 8; k++) {
        const int i = lane + k * 32;       // 250 float4 per row
        if (i < 250) {
            const float4 x = lp[i];
            const float4 s = sp[i];
            sum += __expf(x.x) + __expf(x.y) + __expf(x.z) + __expf(x.w);
            dot += s.x * x.x + s.y * x.y + s.z * x.z + s.w * x.w;
        }
    }

    #pragma unroll
    for (int o = 16; o; o >>= 1) {
        sum += __shfl_xor_sync(0xffffffffu, sum, o);
        dot += __shfl_xor_sync(0xffffffffu, dot, o);
    }

    __shared__ float wsum[WARPS_PER_BLOCK];
    if (lane == 0)
        wsum[warp_in_blk] = __logf(sum) - dot;
    __syncthreads();

    if (threadIdx.x == 0) {
        float acc = 0.0f;
        #pragma unroll
        for (int w = 0; w < WARPS_PER_BLOCK; w++) acc += wsum[w];
        g_partials[blockIdx.x] = acc;
    }
}

// ---------------------------------------------------------------------------
// Kernel 3: reduce 8192 block partials -> scalar mean loss.
// ---------------------------------------------------------------------------
__global__ void final_reduce_kernel(float* __restrict__ out) {
    __shared__ double red[256];
    double acc = 0.0;
    for (int i = threadIdx.x; i < MAIN_BLOCKS; i += 256)
        acc += (double)g_partials[i];
    red[threadIdx.x] = acc;
    __syncthreads();
    for (int s = 128; s > 0; s >>= 1) {
        if (threadIdx.x < s) red[threadIdx.x] += red[threadIdx.x + s];
        __syncthreads();
    }
    if (threadIdx.x == 0)
        out[0] = (float)(red[0] / (double)B);
}

// ---------------------------------------------------------------------------
extern "C" void kernel_launch(void* const* d_in, const int* in_sizes, int n_in,
                              void* d_out, int out_size) {
    const float* logits = (const float*)d_in[0];
    const int* targets = (const int*)d_in[1];
    const float* sim = (const float*)d_in[2];
    float* out = (float*)d_out;

    soft_targets_kernel<<<C, 256>>>(sim);
    soft_ce_main_kernel<<<MAIN_BLOCKS, MAIN_THREADS>>>(logits, targets);
    final_reduce_kernel<<<1, 256>>>(out);
}